// round 3
// baseline (speedup 1.0000x reference)
#include <cuda_runtime.h>

#define Bz 8
#define Hh 384
#define Ww 384
#define HW (384*384)
#define COILS 16
#define EPSn 1e-12f

__device__ float g_ximg[Bz*2*HW];        // (B,2,H,W): real/imag planes
__device__ float g_gram[Bz*27*27];       // per-batch 27x27 Gram (block-upper-triangle valid)
__device__ float g_weff[Bz*2*2*9];       // per-batch effective 2->2 3x3 conv weights

__constant__ unsigned char cPU[45] = {0,0,0,0,0,0,0,0,0, 1,1,1,1,1,1,1,1, 2,2,2,2,2,2,2,
                                      3,3,3,3,3,3, 4,4,4,4,4, 5,5,5,5, 6,6,6, 7,7, 8};
__constant__ unsigned char cPV[45] = {0,1,2,3,4,5,6,7,8, 1,2,3,4,5,6,7,8, 2,3,4,5,6,7,8,
                                      3,4,5,6,7,8, 4,5,6,7,8, 5,6,7,8, 6,7,8, 7,8, 8};

// ---------------- K1 (per batch): coil-combine + zero this batch's gram ----------------
__global__ __launch_bounds__(256) void k_coil_reduce(const float* __restrict__ x,
                                                     const float* __restrict__ sens,
                                                     int b){
    int h = blockIdx.x*blockDim.x + threadIdx.x;     // float4 index within plane [0, HW/2)
    if (h < 729) g_gram[b*729 + h] = 0.f;
    const float4* xq = reinterpret_cast<const float4*>(x)    + (size_t)b*COILS*(HW/2) + h;
    const float4* sq = reinterpret_cast<const float4*>(sens) + (size_t)b*COILS*(HW/2) + h;
    float re0=0.f, im0=0.f, re1=0.f, im1=0.f;
    #pragma unroll
    for (int c = 0; c < COILS; c++){
        float4 a = __ldg(xq + (size_t)c*(HW/2));
        float4 s = __ldg(sq + (size_t)c*(HW/2));
        re0 += a.x*s.x + a.y*s.y;  im0 += a.y*s.x - a.x*s.y;
        re1 += a.z*s.z + a.w*s.w;  im1 += a.w*s.z - a.z*s.w;
    }
    float2* pr = reinterpret_cast<float2*>(g_ximg + (size_t)(b*2+0)*HW);
    float2* pi = reinterpret_cast<float2*>(g_ximg + (size_t)(b*2+1)*HW);
    pr[h] = make_float2(re0, re1);
    pi[h] = make_float2(im0, im1);
}

// ---------------- K2 (per batch): 27x27 Gram via sliding-window ----------------
__global__ __launch_bounds__(256) void k_gram(const float* __restrict__ e, int b){
    __shared__ float sm[3*34*37];     // 3 planes, 34x34 tile+halo, row stride 37
    int ty0 = blockIdx.y*32, tx0 = blockIdx.x*32;
    int tid = threadIdx.x;

    for (int i = tid; i < 3*34*34; i += 256){
        int pl = i / 1156; int r = i - pl*1156;
        int y = r / 34, xx = r - y*34;
        int gy = ty0 + y - 1, gx = tx0 + xx - 1;
        float v = 0.f;
        if (gy >= 0 && gy < Hh && gx >= 0 && gx < Ww){
            int gp = gy*Ww + gx;
            v = (pl < 2) ? g_ximg[(size_t)(b*2+pl)*HW + gp] : __ldg(e + (size_t)b*HW + gp);
        }
        sm[pl*1258 + y*37 + xx] = v;
    }
    __syncthreads();

    int lane = tid & 31;
    float* gb = g_gram + b*729;
    for (int task = tid; task < 1440; task += 256){
        int pair = task >> 5;
        int y    = task & 31;
        int bu = cPU[pair], bv = cPV[pair];
        const float* ru = sm + (bu/3)*1258 + (y + (bu%3))*37;
        const float* rv = sm + (bv/3)*1258 + (y + (bv%3))*37;
        float u0 = ru[0], u1 = ru[1];
        float v0 = rv[0], v1 = rv[1];
        float a00=0,a01=0,a02=0,a10=0,a11=0,a12=0,a20=0,a21=0,a22=0;
        #pragma unroll
        for (int xx = 0; xx < 32; xx++){
            float u2 = ru[xx+2], v2 = rv[xx+2];
            a00 += u0*v0; a01 += u0*v1; a02 += u0*v2;
            a10 += u1*v0; a11 += u1*v1; a12 += u1*v2;
            a20 += u2*v0; a21 += u2*v1; a22 += u2*v2;
            u0 = u1; u1 = u2; v0 = v1; v1 = v2;
        }
        #pragma unroll
        for (int s = 16; s > 0; s >>= 1){
            a00 += __shfl_xor_sync(0xffffffffu, a00, s);
            a01 += __shfl_xor_sync(0xffffffffu, a01, s);
            a02 += __shfl_xor_sync(0xffffffffu, a02, s);
            a10 += __shfl_xor_sync(0xffffffffu, a10, s);
            a11 += __shfl_xor_sync(0xffffffffu, a11, s);
            a12 += __shfl_xor_sync(0xffffffffu, a12, s);
            a20 += __shfl_xor_sync(0xffffffffu, a20, s);
            a21 += __shfl_xor_sync(0xffffffffu, a21, s);
            a22 += __shfl_xor_sync(0xffffffffu, a22, s);
        }
        if (lane == 0){
            float* g0 = gb + (bu*3+0)*27 + bv*3;
            float* g1 = gb + (bu*3+1)*27 + bv*3;
            float* g2 = gb + (bu*3+2)*27 + bv*3;
            atomicAdd(g0+0,a00); atomicAdd(g0+1,a01); atomicAdd(g0+2,a02);
            atomicAdd(g1+0,a10); atomicAdd(g1+1,a11); atomicAdd(g1+2,a12);
            atomicAdd(g2+0,a20); atomicAdd(g2+1,a21); atomicAdd(g2+2,a22);
        }
    }
}

// ---------------- K3 (per batch): attention on Gram, fold into Weff ----------------
__global__ __launch_bounds__(256) void k_attn(const float* __restrict__ w_im1,
                                              const float* __restrict__ w_im2,
                                              const float* __restrict__ w_e,
                                              const float* __restrict__ w_proj,
                                              const float* __restrict__ a1,
                                              int b){
    __shared__ float sG[27][27];
    __shared__ float sT[192][9];
    __shared__ float sqq[192];
    __shared__ float skk[192];
    __shared__ float sAt[192][24];
    __shared__ float sWf[2][192];
    __shared__ float s_we[192*9];
    __shared__ float s_wp[2*192];
    __shared__ float s_a1[8];
    __shared__ float spart[36][6];
    int tid = threadIdx.x;

    for (int i = tid; i < 192*9; i += 256) s_we[i] = __ldg(w_e + i);
    for (int i = tid; i < 2*192; i += 256) s_wp[i] = __ldg(w_proj + i);
    if (tid < 8) s_a1[tid] = __ldg(a1 + tid);
    for (int i = tid; i < 729; i += 256){
        int u = i/27, v = i - u*27;
        int lo = u < v ? u : v, hi = u < v ? v : u;
        sG[u][v] = g_gram[b*729 + lo*27 + hi];
    }
    __syncthreads();

    if (tid < 192){
        int j = tid;
        float aq[18];
        #pragma unroll
        for (int u = 0; u < 18; u++){
            int base = u/9, tt = u - base*9;
            aq[u] = __ldg(w_im1 + j*2 + base) * __ldg(w_im2 + j*9 + tt);
        }
        float qq = 0.f;
        #pragma unroll
        for (int u = 0; u < 18; u++){
            float s = 0.f;
            #pragma unroll
            for (int v = 0; v < 18; v++) s += aq[v]*sG[u][v];
            qq += aq[u]*s;
        }
        sqq[j] = qq;
        #pragma unroll
        for (int tt = 0; tt < 9; tt++){
            float s = 0.f;
            #pragma unroll
            for (int u = 0; u < 18; u++) s += aq[u]*sG[u][18+tt];
            sT[j][tt] = s;
        }
        float kk = 0.f;
        #pragma unroll
        for (int t1 = 0; t1 < 9; t1++){
            float s = 0.f;
            #pragma unroll
            for (int t2 = 0; t2 < 9; t2++) s += s_we[j*9+t2]*sG[18+t1][18+t2];
            kk += s_we[j*9+t1]*s;
        }
        skk[j] = kk;
    }
    __syncthreads();

    for (int i = tid; i < 192*24; i += 256){
        int row = i / 24, d = i - row*24;
        int h = row / 24;
        int jk = h*24 + d;
        float s = 0.f;
        #pragma unroll
        for (int tt = 0; tt < 9; tt++) s += sT[row][tt] * s_we[jk*9+tt];
        float qn = fmaxf(sqrtf(fmaxf(sqq[row], 0.f)), EPSn);
        float kn = fmaxf(sqrtf(fmaxf(skk[jk], 0.f)), EPSn);
        sAt[row][d] = s * s_a1[h] / (qn*kn);
    }
    __syncthreads();

    if (tid < 192){
        float m = -1e30f;
        #pragma unroll
        for (int d = 0; d < 24; d++) m = fmaxf(m, sAt[tid][d]);
        float ex[24]; float ssum = 0.f;
        #pragma unroll
        for (int d = 0; d < 24; d++){ ex[d] = __expf(sAt[tid][d] - m); ssum += ex[d]; }
        float inv = 1.f/ssum;
        #pragma unroll
        for (int d = 0; d < 24; d++) sAt[tid][d] = ex[d]*inv;
    }
    __syncthreads();

    for (int i = tid; i < 2*192; i += 256){
        int ch = i / 192, jp = i - ch*192;
        int h = jp / 24, d = jp - h*24;
        float s = 0.f;
        #pragma unroll
        for (int c = 0; c < 24; c++) s += s_wp[ch*192 + h*24 + c] * sAt[h*24+c][d];
        sWf[ch][jp] = s;
    }
    __syncthreads();

    if (tid < 216){
        int o = tid / 6, q = tid - (tid/6)*6;
        int ch = o / 18, r = o - ch*18;
        int base = r / 9, tt = r - base*9;
        float s = 0.f;
        #pragma unroll
        for (int k = 0; k < 32; k++){
            int jp = q*32 + k;
            s += sWf[ch][jp] * __ldg(w_im1 + (192+jp)*2 + base) * __ldg(w_im2 + (192+jp)*9 + tt);
        }
        spart[o][q] = s;
    }
    __syncthreads();
    if (tid < 36){
        float s = spart[tid][0]+spart[tid][1]+spart[tid][2]+spart[tid][3]+spart[tid][4]+spart[tid][5];
        g_weff[b*36 + tid] = s;
    }
}

// ---------------- K4 (per batch): out = ximg + Weff(*)ximg, coil-expand ----------------
__global__ __launch_bounds__(256) void k_output(const float* __restrict__ sens,
                                                float* __restrict__ out,
                                                int b){
    __shared__ float sw[36];
    __shared__ float sX[2][10][66];
    int ty0 = blockIdx.y*8, tx0 = blockIdx.x*64;
    int tid = threadIdx.x;
    if (tid < 36) sw[tid] = g_weff[b*36 + tid];
    for (int i = tid; i < 2*10*66; i += 256){
        int pl = i/660; int r = i - pl*660;
        int y = r/66, xx = r - y*66;
        int gy = ty0 + y - 1, gx = tx0 + xx - 1;
        float v = 0.f;
        if (gy >= 0 && gy < Hh && gx >= 0 && gx < Ww) v = g_ximg[(size_t)(b*2+pl)*HW + gy*Ww + gx];
        sX[pl][y][xx] = v;
    }
    __syncthreads();

    int py  = tid >> 5;
    int px2 = (tid & 31)*2;
    float o0a = sX[0][py+1][px2+1], o0b = sX[0][py+1][px2+2];
    float o1a = sX[1][py+1][px2+1], o1b = sX[1][py+1][px2+2];
    #pragma unroll
    for (int base = 0; base < 2; base++){
        #pragma unroll
        for (int dy = 0; dy < 3; dy++){
            float w0 = sX[base][py+dy][px2+0];
            float w1 = sX[base][py+dy][px2+1];
            float w2 = sX[base][py+dy][px2+2];
            float w3 = sX[base][py+dy][px2+3];
            float c00 = sw[0*18 + base*9 + dy*3 + 0];
            float c01 = sw[0*18 + base*9 + dy*3 + 1];
            float c02 = sw[0*18 + base*9 + dy*3 + 2];
            float c10 = sw[1*18 + base*9 + dy*3 + 0];
            float c11 = sw[1*18 + base*9 + dy*3 + 1];
            float c12 = sw[1*18 + base*9 + dy*3 + 2];
            o0a += c00*w0 + c01*w1 + c02*w2;
            o0b += c00*w1 + c01*w2 + c02*w3;
            o1a += c10*w0 + c11*w1 + c12*w2;
            o1b += c10*w1 + c11*w2 + c12*w3;
        }
    }
    int p  = (ty0+py)*Ww + tx0 + px2;   // even
    int h4 = p >> 1;
    const float4* sp = reinterpret_cast<const float4*>(sens) + (size_t)b*COILS*(HW/2) + h4;
    float4*       op = reinterpret_cast<float4*>(out)        + (size_t)b*COILS*(HW/2) + h4;
    #pragma unroll
    for (int c = 0; c < COILS; c++){
        float4 s = __ldg(sp + (size_t)c*(HW/2));
        float4 r;
        r.x = o0a*s.x - o1a*s.y;
        r.y = o0a*s.y + o1a*s.x;
        r.z = o0b*s.z - o1b*s.w;
        r.w = o0b*s.w + o1b*s.z;
        op[(size_t)c*(HW/2)] = r;
    }
}

// ---- host-side stream/event plumbing (created at load time; host objects only) ----
static cudaStream_t g_s2;
static cudaEvent_t  g_ev1[Bz], g_ev2[Bz];
namespace {
struct StreamInit {
    StreamInit(){
        cudaStreamCreateWithFlags(&g_s2, cudaStreamNonBlocking);
        for (int i = 0; i < Bz; i++){
            cudaEventCreateWithFlags(&g_ev1[i], cudaEventDisableTiming);
            cudaEventCreateWithFlags(&g_ev2[i], cudaEventDisableTiming);
        }
    }
};
static StreamInit g_stream_init;
}

extern "C" void kernel_launch(void* const* d_in, const int* in_sizes, int n_in,
                              void* d_out, int out_size){
    const float* x      = (const float*)d_in[0];
    const float* e      = (const float*)d_in[1];
    const float* sens   = (const float*)d_in[2];
    const float* w_im1  = (const float*)d_in[3];
    const float* w_im2  = (const float*)d_in[4];
    const float* w_e    = (const float*)d_in[5];
    const float* w_proj = (const float*)d_in[6];
    const float* a1     = (const float*)d_in[7];
    float* out = (float*)d_out;

    // stream0 (capture stream): K1 per batch; stream2: gram+attn per batch.
    for (int b = 0; b < Bz; b++){
        k_coil_reduce<<<(HW/2)/256, 256>>>(x, sens, b);
        cudaEventRecord(g_ev1[b], 0);
        cudaStreamWaitEvent(g_s2, g_ev1[b], 0);
        k_gram<<<dim3(Ww/32, Hh/32), 256, 0, g_s2>>>(e, b);
        k_attn<<<1, 256, 0, g_s2>>>(w_im1, w_im2, w_e, w_proj, a1, b);
        cudaEventRecord(g_ev2[b], g_s2);
    }
    for (int b = 0; b < Bz; b++){
        cudaStreamWaitEvent(0, g_ev2[b], 0);
        k_output<<<dim3(Ww/64, Hh/8), 256>>>(sens, out, b);
    }
}

// round 4
// speedup vs baseline: 1.9883x; 1.9883x over previous
#include <cuda_runtime.h>

#define Bz 8
#define GRP 4
#define Hh 384
#define Ww 384
#define HW (384*384)
#define COILS 16
#define EPSn 1e-12f

__device__ float g_ximg[Bz*2*HW];        // (B,2,H,W): real/imag planes
__device__ float g_gram[Bz*27*27];       // per-batch 27x27 Gram (block-upper-triangle valid)
__device__ float g_weff[Bz*2*2*9];       // per-batch effective 2->2 3x3 conv weights

__constant__ unsigned char cPU[45] = {0,0,0,0,0,0,0,0,0, 1,1,1,1,1,1,1,1, 2,2,2,2,2,2,2,
                                      3,3,3,3,3,3, 4,4,4,4,4, 5,5,5,5, 6,6,6, 7,7, 8};
__constant__ unsigned char cPV[45] = {0,1,2,3,4,5,6,7,8, 1,2,3,4,5,6,7,8, 2,3,4,5,6,7,8,
                                      3,4,5,6,7,8, 4,5,6,7,8, 5,6,7,8, 6,7,8, 7,8, 8};

// ---------------- K1 (per 4-batch group): coil-combine + zero group's gram ----------------
__global__ __launch_bounds__(256) void k_coil_reduce(const float* __restrict__ x,
                                                     const float* __restrict__ sens,
                                                     int b0){
    int idx = blockIdx.x*blockDim.x + threadIdx.x;   // over GRP*HW/2
    if (idx < GRP*729) g_gram[b0*729 + idx] = 0.f;
    int bl = idx / (HW/2);
    int h  = idx - bl*(HW/2);
    int b  = b0 + bl;
    const float4* xq = reinterpret_cast<const float4*>(x)    + (size_t)b*COILS*(HW/2) + h;
    const float4* sq = reinterpret_cast<const float4*>(sens) + (size_t)b*COILS*(HW/2) + h;
    float re0=0.f, im0=0.f, re1=0.f, im1=0.f;
    #pragma unroll
    for (int c = 0; c < COILS; c++){
        float4 a = __ldg(xq + (size_t)c*(HW/2));
        float4 s = __ldg(sq + (size_t)c*(HW/2));
        re0 += a.x*s.x + a.y*s.y;  im0 += a.y*s.x - a.x*s.y;
        re1 += a.z*s.z + a.w*s.w;  im1 += a.w*s.z - a.z*s.w;
    }
    float2* pr = reinterpret_cast<float2*>(g_ximg + (size_t)(b*2+0)*HW);
    float2* pi = reinterpret_cast<float2*>(g_ximg + (size_t)(b*2+1)*HW);
    pr[h] = make_float2(re0, re1);
    pi[h] = make_float2(im0, im1);
}

// ---------------- K2 (per group): 27x27 Gram via sliding-window ----------------
__global__ __launch_bounds__(256) void k_gram(const float* __restrict__ e, int b0){
    __shared__ float sm[3*34*37];     // 3 planes, 34x34 tile+halo, row stride 37
    int b   = b0 + blockIdx.z;
    int ty0 = blockIdx.y*32, tx0 = blockIdx.x*32;
    int tid = threadIdx.x;

    for (int i = tid; i < 3*34*34; i += 256){
        int pl = i / 1156; int r = i - pl*1156;
        int y = r / 34, xx = r - y*34;
        int gy = ty0 + y - 1, gx = tx0 + xx - 1;
        float v = 0.f;
        if (gy >= 0 && gy < Hh && gx >= 0 && gx < Ww){
            int gp = gy*Ww + gx;
            v = (pl < 2) ? g_ximg[(size_t)(b*2+pl)*HW + gp] : __ldg(e + (size_t)b*HW + gp);
        }
        sm[pl*1258 + y*37 + xx] = v;
    }
    __syncthreads();

    int lane = tid & 31;
    float* gb = g_gram + b*729;
    for (int task = tid; task < 1440; task += 256){
        int pair = task >> 5;
        int y    = task & 31;
        int bu = cPU[pair], bv = cPV[pair];
        const float* ru = sm + (bu/3)*1258 + (y + (bu%3))*37;
        const float* rv = sm + (bv/3)*1258 + (y + (bv%3))*37;
        float u0 = ru[0], u1 = ru[1];
        float v0 = rv[0], v1 = rv[1];
        float a00=0,a01=0,a02=0,a10=0,a11=0,a12=0,a20=0,a21=0,a22=0;
        #pragma unroll
        for (int xx = 0; xx < 32; xx++){
            float u2 = ru[xx+2], v2 = rv[xx+2];
            a00 += u0*v0; a01 += u0*v1; a02 += u0*v2;
            a10 += u1*v0; a11 += u1*v1; a12 += u1*v2;
            a20 += u2*v0; a21 += u2*v1; a22 += u2*v2;
            u0 = u1; u1 = u2; v0 = v1; v1 = v2;
        }
        #pragma unroll
        for (int s = 16; s > 0; s >>= 1){
            a00 += __shfl_xor_sync(0xffffffffu, a00, s);
            a01 += __shfl_xor_sync(0xffffffffu, a01, s);
            a02 += __shfl_xor_sync(0xffffffffu, a02, s);
            a10 += __shfl_xor_sync(0xffffffffu, a10, s);
            a11 += __shfl_xor_sync(0xffffffffu, a11, s);
            a12 += __shfl_xor_sync(0xffffffffu, a12, s);
            a20 += __shfl_xor_sync(0xffffffffu, a20, s);
            a21 += __shfl_xor_sync(0xffffffffu, a21, s);
            a22 += __shfl_xor_sync(0xffffffffu, a22, s);
        }
        if (lane == 0){
            float* g0 = gb + (bu*3+0)*27 + bv*3;
            float* g1 = gb + (bu*3+1)*27 + bv*3;
            float* g2 = gb + (bu*3+2)*27 + bv*3;
            atomicAdd(g0+0,a00); atomicAdd(g0+1,a01); atomicAdd(g0+2,a02);
            atomicAdd(g1+0,a10); atomicAdd(g1+1,a11); atomicAdd(g1+2,a12);
            atomicAdd(g2+0,a20); atomicAdd(g2+1,a21); atomicAdd(g2+2,a22);
        }
    }
}

// ---------------- K3 (per group): attention on Gram, fold into Weff ----------------
__global__ __launch_bounds__(256) void k_attn(const float* __restrict__ w_im1,
                                              const float* __restrict__ w_im2,
                                              const float* __restrict__ w_e,
                                              const float* __restrict__ w_proj,
                                              const float* __restrict__ a1,
                                              int b0){
    __shared__ float sG[27][27];
    __shared__ float sT[192][9];
    __shared__ float sqq[192];
    __shared__ float skk[192];
    __shared__ float sAt[192][24];
    __shared__ float sWf[2][192];
    __shared__ float s_we[192*9];
    __shared__ float s_wp[2*192];
    __shared__ float s_a1[8];
    __shared__ float spart[36][6];
    int b = b0 + blockIdx.x;
    int tid = threadIdx.x;

    for (int i = tid; i < 192*9; i += 256) s_we[i] = __ldg(w_e + i);
    for (int i = tid; i < 2*192; i += 256) s_wp[i] = __ldg(w_proj + i);
    if (tid < 8) s_a1[tid] = __ldg(a1 + tid);
    for (int i = tid; i < 729; i += 256){
        int u = i/27, v = i - u*27;
        int lo = u < v ? u : v, hi = u < v ? v : u;
        sG[u][v] = g_gram[b*729 + lo*27 + hi];
    }
    __syncthreads();

    if (tid < 192){
        int j = tid;
        float aq[18];
        #pragma unroll
        for (int u = 0; u < 18; u++){
            int base = u/9, tt = u - base*9;
            aq[u] = __ldg(w_im1 + j*2 + base) * __ldg(w_im2 + j*9 + tt);
        }
        float qq = 0.f;
        #pragma unroll
        for (int u = 0; u < 18; u++){
            float s = 0.f;
            #pragma unroll
            for (int v = 0; v < 18; v++) s += aq[v]*sG[u][v];
            qq += aq[u]*s;
        }
        sqq[j] = qq;
        #pragma unroll
        for (int tt = 0; tt < 9; tt++){
            float s = 0.f;
            #pragma unroll
            for (int u = 0; u < 18; u++) s += aq[u]*sG[u][18+tt];
            sT[j][tt] = s;
        }
        float kk = 0.f;
        #pragma unroll
        for (int t1 = 0; t1 < 9; t1++){
            float s = 0.f;
            #pragma unroll
            for (int t2 = 0; t2 < 9; t2++) s += s_we[j*9+t2]*sG[18+t1][18+t2];
            kk += s_we[j*9+t1]*s;
        }
        skk[j] = kk;
    }
    __syncthreads();

    for (int i = tid; i < 192*24; i += 256){
        int row = i / 24, d = i - row*24;
        int h = row / 24;
        int jk = h*24 + d;
        float s = 0.f;
        #pragma unroll
        for (int tt = 0; tt < 9; tt++) s += sT[row][tt] * s_we[jk*9+tt];
        float qn = fmaxf(sqrtf(fmaxf(sqq[row], 0.f)), EPSn);
        float kn = fmaxf(sqrtf(fmaxf(skk[jk], 0.f)), EPSn);
        sAt[row][d] = s * s_a1[h] / (qn*kn);
    }
    __syncthreads();

    if (tid < 192){
        float m = -1e30f;
        #pragma unroll
        for (int d = 0; d < 24; d++) m = fmaxf(m, sAt[tid][d]);
        float ex[24]; float ssum = 0.f;
        #pragma unroll
        for (int d = 0; d < 24; d++){ ex[d] = __expf(sAt[tid][d] - m); ssum += ex[d]; }
        float inv = 1.f/ssum;
        #pragma unroll
        for (int d = 0; d < 24; d++) sAt[tid][d] = ex[d]*inv;
    }
    __syncthreads();

    for (int i = tid; i < 2*192; i += 256){
        int ch = i / 192, jp = i - ch*192;
        int h = jp / 24, d = jp - h*24;
        float s = 0.f;
        #pragma unroll
        for (int c = 0; c < 24; c++) s += s_wp[ch*192 + h*24 + c] * sAt[h*24+c][d];
        sWf[ch][jp] = s;
    }
    __syncthreads();

    if (tid < 216){
        int o = tid / 6, q = tid - (tid/6)*6;
        int ch = o / 18, r = o - ch*18;
        int base = r / 9, tt = r - base*9;
        float s = 0.f;
        #pragma unroll
        for (int k = 0; k < 32; k++){
            int jp = q*32 + k;
            s += sWf[ch][jp] * __ldg(w_im1 + (192+jp)*2 + base) * __ldg(w_im2 + (192+jp)*9 + tt);
        }
        spart[o][q] = s;
    }
    __syncthreads();
    if (tid < 36){
        float s = spart[tid][0]+spart[tid][1]+spart[tid][2]+spart[tid][3]+spart[tid][4]+spart[tid][5];
        g_weff[b*36 + tid] = s;
    }
}

// ---------------- K4 (per group): out = ximg + Weff(*)ximg, coil-expand ----------------
__global__ __launch_bounds__(256) void k_output(const float* __restrict__ sens,
                                                float* __restrict__ out,
                                                int b0){
    __shared__ float sw[36];
    __shared__ float sX[2][10][66];
    int b   = b0 + blockIdx.z;
    int ty0 = blockIdx.y*8, tx0 = blockIdx.x*64;
    int tid = threadIdx.x;
    if (tid < 36) sw[tid] = g_weff[b*36 + tid];
    for (int i = tid; i < 2*10*66; i += 256){
        int pl = i/660; int r = i - pl*660;
        int y = r/66, xx = r - y*66;
        int gy = ty0 + y - 1, gx = tx0 + xx - 1;
        float v = 0.f;
        if (gy >= 0 && gy < Hh && gx >= 0 && gx < Ww) v = g_ximg[(size_t)(b*2+pl)*HW + gy*Ww + gx];
        sX[pl][y][xx] = v;
    }
    __syncthreads();

    int py  = tid >> 5;
    int px2 = (tid & 31)*2;
    float o0a = sX[0][py+1][px2+1], o0b = sX[0][py+1][px2+2];
    float o1a = sX[1][py+1][px2+1], o1b = sX[1][py+1][px2+2];
    #pragma unroll
    for (int base = 0; base < 2; base++){
        #pragma unroll
        for (int dy = 0; dy < 3; dy++){
            float w0 = sX[base][py+dy][px2+0];
            float w1 = sX[base][py+dy][px2+1];
            float w2 = sX[base][py+dy][px2+2];
            float w3 = sX[base][py+dy][px2+3];
            float c00 = sw[0*18 + base*9 + dy*3 + 0];
            float c01 = sw[0*18 + base*9 + dy*3 + 1];
            float c02 = sw[0*18 + base*9 + dy*3 + 2];
            float c10 = sw[1*18 + base*9 + dy*3 + 0];
            float c11 = sw[1*18 + base*9 + dy*3 + 1];
            float c12 = sw[1*18 + base*9 + dy*3 + 2];
            o0a += c00*w0 + c01*w1 + c02*w2;
            o0b += c00*w1 + c01*w2 + c02*w3;
            o1a += c10*w0 + c11*w1 + c12*w2;
            o1b += c10*w1 + c11*w2 + c12*w3;
        }
    }
    int p  = (ty0+py)*Ww + tx0 + px2;   // even
    int h4 = p >> 1;
    const float4* sp = reinterpret_cast<const float4*>(sens) + (size_t)b*COILS*(HW/2) + h4;
    float4*       op = reinterpret_cast<float4*>(out)        + (size_t)b*COILS*(HW/2) + h4;
    #pragma unroll
    for (int c = 0; c < COILS; c++){
        float4 s = __ldg(sp + (size_t)c*(HW/2));
        float4 r;
        r.x = o0a*s.x - o1a*s.y;
        r.y = o0a*s.y + o1a*s.x;
        r.z = o0b*s.z - o1b*s.w;
        r.w = o0b*s.w + o1b*s.z;
        op[(size_t)c*(HW/2)] = r;
    }
}

// ---- host-side stream/event plumbing (created at load time; host objects only) ----
static cudaStream_t g_s2;
static cudaEvent_t  g_ev1[2], g_ev2[2];
namespace {
struct StreamInit {
    StreamInit(){
        cudaStreamCreateWithFlags(&g_s2, cudaStreamNonBlocking);
        for (int i = 0; i < 2; i++){
            cudaEventCreateWithFlags(&g_ev1[i], cudaEventDisableTiming);
            cudaEventCreateWithFlags(&g_ev2[i], cudaEventDisableTiming);
        }
    }
};
static StreamInit g_stream_init;
}

extern "C" void kernel_launch(void* const* d_in, const int* in_sizes, int n_in,
                              void* d_out, int out_size){
    const float* x      = (const float*)d_in[0];
    const float* e      = (const float*)d_in[1];
    const float* sens   = (const float*)d_in[2];
    const float* w_im1  = (const float*)d_in[3];
    const float* w_im2  = (const float*)d_in[4];
    const float* w_e    = (const float*)d_in[5];
    const float* w_proj = (const float*)d_in[6];
    const float* a1     = (const float*)d_in[7];
    float* out = (float*)d_out;

    for (int g = 0; g < 2; g++){
        int b0 = g*GRP;
        k_coil_reduce<<<(GRP*HW/2)/256, 256>>>(x, sens, b0);
        cudaEventRecord(g_ev1[g], 0);
        cudaStreamWaitEvent(g_s2, g_ev1[g], 0);
        k_gram<<<dim3(Ww/32, Hh/32, GRP), 256, 0, g_s2>>>(e, b0);
        k_attn<<<GRP, 256, 0, g_s2>>>(w_im1, w_im2, w_e, w_proj, a1, b0);
        cudaEventRecord(g_ev2[g], g_s2);
    }
    for (int g = 0; g < 2; g++){
        cudaStreamWaitEvent(0, g_ev2[g], 0);
        k_output<<<dim3(Ww/64, Hh/8, GRP), 256>>>(sens, out, g*GRP);
    }
}

// round 5
// speedup vs baseline: 2.1965x; 1.1047x over previous
#include <cuda_runtime.h>

#define Bz 8
#define Hh 384
#define Ww 384
#define HW (384*384)
#define COILS 16
#define EPSn 1e-12f

__device__ float g_ximg[Bz*2*HW];        // (B,2,H,W): real/imag planes
__device__ float g_gram[Bz*27*27];       // per-batch 27x27 Gram (block-upper-triangle valid)
__device__ float g_weff[Bz*2*2*9];       // per-batch effective 2->2 3x3 conv weights

__constant__ unsigned char cPU[45] = {0,0,0,0,0,0,0,0,0, 1,1,1,1,1,1,1,1, 2,2,2,2,2,2,2,
                                      3,3,3,3,3,3, 4,4,4,4,4, 5,5,5,5, 6,6,6, 7,7, 8};
__constant__ unsigned char cPV[45] = {0,1,2,3,4,5,6,7,8, 1,2,3,4,5,6,7,8, 2,3,4,5,6,7,8,
                                      3,4,5,6,7,8, 4,5,6,7,8, 5,6,7,8, 6,7,8, 7,8, 8};

// ------- K1' (fused): coil-combine into smem tile (with halo) + store interior + Gram -------
__global__ __launch_bounds__(256) void k_cgram(const float* __restrict__ x,
                                               const float* __restrict__ sens,
                                               const float* __restrict__ e){
    __shared__ float sm[3*34*37];     // planes: ximg_re, ximg_im, e; 34x34 tile+halo, stride 37
    int b   = blockIdx.z;
    int ty0 = blockIdx.y*32, tx0 = blockIdx.x*32;
    int tid = threadIdx.x;

    const float2* xb = reinterpret_cast<const float2*>(x)    + (size_t)b*COILS*HW;
    const float2* sb = reinterpret_cast<const float2*>(sens) + (size_t)b*COILS*HW;

    for (int i = tid; i < 34*34; i += 256){
        int y = i / 34, xx = i - y*34;
        int gy = ty0 + y - 1, gx = tx0 + xx - 1;
        float re = 0.f, im = 0.f, ev = 0.f;
        bool in = (gy >= 0 && gy < Hh && gx >= 0 && gx < Ww);
        if (in){
            int p = gy*Ww + gx;
            const float2* xp = xb + p;
            const float2* sp = sb + p;
            #pragma unroll
            for (int c = 0; c < COILS; c++){
                float2 a = __ldg(xp + (size_t)c*HW);
                float2 s = __ldg(sp + (size_t)c*HW);
                re += a.x*s.x + a.y*s.y;   // cmul(a, conj(s)).re
                im += a.y*s.x - a.x*s.y;   // cmul(a, conj(s)).im
            }
            ev = __ldg(e + (size_t)b*HW + p);
        }
        sm[0*1258 + y*37 + xx] = re;
        sm[1*1258 + y*37 + xx] = im;
        sm[2*1258 + y*37 + xx] = ev;
        if (in && y >= 1 && y < 33 && xx >= 1 && xx < 33){
            int p = gy*Ww + gx;
            g_ximg[(size_t)(b*2+0)*HW + p] = re;
            g_ximg[(size_t)(b*2+1)*HW + p] = im;
        }
    }
    __syncthreads();

    int lane = tid & 31;
    float* gb = g_gram + b*729;
    // 1440 tasks = 45 block-pairs x 32 rows; each warp-iteration owns exactly one pair.
    for (int task = tid; task < 1440; task += 256){
        int pair = task >> 5;
        int y    = task & 31;
        int bu = cPU[pair], bv = cPV[pair];
        const float* ru = sm + (bu/3)*1258 + (y + (bu%3))*37;
        const float* rv = sm + (bv/3)*1258 + (y + (bv%3))*37;
        float u0 = ru[0], u1 = ru[1];
        float v0 = rv[0], v1 = rv[1];
        float a00=0,a01=0,a02=0,a10=0,a11=0,a12=0,a20=0,a21=0,a22=0;
        #pragma unroll
        for (int xx = 0; xx < 32; xx++){
            float u2 = ru[xx+2], v2 = rv[xx+2];
            a00 += u0*v0; a01 += u0*v1; a02 += u0*v2;
            a10 += u1*v0; a11 += u1*v1; a12 += u1*v2;
            a20 += u2*v0; a21 += u2*v1; a22 += u2*v2;
            u0 = u1; u1 = u2; v0 = v1; v1 = v2;
        }
        #pragma unroll
        for (int s = 16; s > 0; s >>= 1){
            a00 += __shfl_xor_sync(0xffffffffu, a00, s);
            a01 += __shfl_xor_sync(0xffffffffu, a01, s);
            a02 += __shfl_xor_sync(0xffffffffu, a02, s);
            a10 += __shfl_xor_sync(0xffffffffu, a10, s);
            a11 += __shfl_xor_sync(0xffffffffu, a11, s);
            a12 += __shfl_xor_sync(0xffffffffu, a12, s);
            a20 += __shfl_xor_sync(0xffffffffu, a20, s);
            a21 += __shfl_xor_sync(0xffffffffu, a21, s);
            a22 += __shfl_xor_sync(0xffffffffu, a22, s);
        }
        if (lane == 0){
            float* g0 = gb + (bu*3+0)*27 + bv*3;
            float* g1 = gb + (bu*3+1)*27 + bv*3;
            float* g2 = gb + (bu*3+2)*27 + bv*3;
            atomicAdd(g0+0,a00); atomicAdd(g0+1,a01); atomicAdd(g0+2,a02);
            atomicAdd(g1+0,a10); atomicAdd(g1+1,a11); atomicAdd(g1+2,a12);
            atomicAdd(g2+0,a20); atomicAdd(g2+1,a21); atomicAdd(g2+2,a22);
        }
    }
}

// ---------------- K3: per-batch attention on Gram, fold into Weff ----------------
__global__ __launch_bounds__(256) void k_attn(const float* __restrict__ w_im1,
                                              const float* __restrict__ w_im2,
                                              const float* __restrict__ w_e,
                                              const float* __restrict__ w_proj,
                                              const float* __restrict__ a1){
    __shared__ float sG[27][27];
    __shared__ float sT[192][9];
    __shared__ float sqq[192];
    __shared__ float skk[192];
    __shared__ float sAt[192][24];
    __shared__ float sWf[2][192];
    __shared__ float s_we[192*9];
    __shared__ float s_wp[2*192];
    __shared__ float s_a1[8];
    __shared__ float spart[36][6];
    int b = blockIdx.x;
    int tid = threadIdx.x;

    for (int i = tid; i < 192*9; i += 256) s_we[i] = __ldg(w_e + i);
    for (int i = tid; i < 2*192; i += 256) s_wp[i] = __ldg(w_proj + i);
    if (tid < 8) s_a1[tid] = __ldg(a1 + tid);
    for (int i = tid; i < 729; i += 256){
        int u = i/27, v = i - u*27;
        int lo = u < v ? u : v, hi = u < v ? v : u;
        sG[u][v] = g_gram[b*729 + lo*27 + hi];
    }
    __syncthreads();

    if (tid < 192){
        int j = tid;
        float aq[18];
        #pragma unroll
        for (int u = 0; u < 18; u++){
            int base = u/9, tt = u - base*9;
            aq[u] = __ldg(w_im1 + j*2 + base) * __ldg(w_im2 + j*9 + tt);
        }
        float qq = 0.f;
        #pragma unroll
        for (int u = 0; u < 18; u++){
            float s = 0.f;
            #pragma unroll
            for (int v = 0; v < 18; v++) s += aq[v]*sG[u][v];
            qq += aq[u]*s;
        }
        sqq[j] = qq;
        #pragma unroll
        for (int tt = 0; tt < 9; tt++){
            float s = 0.f;
            #pragma unroll
            for (int u = 0; u < 18; u++) s += aq[u]*sG[u][18+tt];
            sT[j][tt] = s;
        }
        float kk = 0.f;
        #pragma unroll
        for (int t1 = 0; t1 < 9; t1++){
            float s = 0.f;
            #pragma unroll
            for (int t2 = 0; t2 < 9; t2++) s += s_we[j*9+t2]*sG[18+t1][18+t2];
            kk += s_we[j*9+t1]*s;
        }
        skk[j] = kk;
    }
    __syncthreads();

    for (int i = tid; i < 192*24; i += 256){
        int row = i / 24, d = i - row*24;
        int h = row / 24;
        int jk = h*24 + d;
        float s = 0.f;
        #pragma unroll
        for (int tt = 0; tt < 9; tt++) s += sT[row][tt] * s_we[jk*9+tt];
        // max(sqrt(q),1e-12) equivalent via guarded rsqrt (values >= 1e-24)
        float rq = rsqrtf(fmaxf(sqq[row], 1e-24f));
        float rk = rsqrtf(fmaxf(skk[jk],  1e-24f));
        sAt[row][d] = s * s_a1[h] * rq * rk;
    }
    __syncthreads();

    if (tid < 192){
        float m = -1e30f;
        #pragma unroll
        for (int d = 0; d < 24; d++) m = fmaxf(m, sAt[tid][d]);
        float ex[24]; float ssum = 0.f;
        #pragma unroll
        for (int d = 0; d < 24; d++){ ex[d] = __expf(sAt[tid][d] - m); ssum += ex[d]; }
        float inv = 1.f/ssum;
        #pragma unroll
        for (int d = 0; d < 24; d++) sAt[tid][d] = ex[d]*inv;
    }
    __syncthreads();

    for (int i = tid; i < 2*192; i += 256){
        int ch = i / 192, jp = i - ch*192;
        int h = jp / 24, d = jp - h*24;
        float s = 0.f;
        #pragma unroll
        for (int c = 0; c < 24; c++) s += s_wp[ch*192 + h*24 + c] * sAt[h*24+c][d];
        sWf[ch][jp] = s;
    }
    __syncthreads();

    if (tid < 216){
        int o = tid / 6, q = tid - (tid/6)*6;
        int ch = o / 18, r = o - ch*18;
        int base = r / 9, tt = r - base*9;
        float s = 0.f;
        #pragma unroll
        for (int k = 0; k < 32; k++){
            int jp = q*32 + k;
            s += sWf[ch][jp] * __ldg(w_im1 + (192+jp)*2 + base) * __ldg(w_im2 + (192+jp)*9 + tt);
        }
        spart[o][q] = s;
    }
    __syncthreads();
    if (tid < 36){
        float s = spart[tid][0]+spart[tid][1]+spart[tid][2]+spart[tid][3]+spart[tid][4]+spart[tid][5];
        g_weff[b*36 + tid] = s;
    }
}

// ---------------- K4: out = ximg + Weff(*)ximg, then coil-expand (2 px/thread) ----------------
__global__ __launch_bounds__(256) void k_output(const float* __restrict__ sens,
                                                float* __restrict__ out){
    __shared__ float sw[36];
    __shared__ float sX[2][10][66];
    int b   = blockIdx.z;
    int ty0 = blockIdx.y*8, tx0 = blockIdx.x*64;
    int tid = threadIdx.x;
    if (tid < 36) sw[tid] = g_weff[b*36 + tid];
    for (int i = tid; i < 2*10*66; i += 256){
        int pl = i/660; int r = i - pl*660;
        int y = r/66, xx = r - y*66;
        int gy = ty0 + y - 1, gx = tx0 + xx - 1;
        float v = 0.f;
        if (gy >= 0 && gy < Hh && gx >= 0 && gx < Ww) v = g_ximg[(size_t)(b*2+pl)*HW + gy*Ww + gx];
        sX[pl][y][xx] = v;
    }
    __syncthreads();

    int py  = tid >> 5;
    int px2 = (tid & 31)*2;
    float o0a = sX[0][py+1][px2+1], o0b = sX[0][py+1][px2+2];
    float o1a = sX[1][py+1][px2+1], o1b = sX[1][py+1][px2+2];
    #pragma unroll
    for (int base = 0; base < 2; base++){
        #pragma unroll
        for (int dy = 0; dy < 3; dy++){
            float w0 = sX[base][py+dy][px2+0];
            float w1 = sX[base][py+dy][px2+1];
            float w2 = sX[base][py+dy][px2+2];
            float w3 = sX[base][py+dy][px2+3];
            float c00 = sw[0*18 + base*9 + dy*3 + 0];
            float c01 = sw[0*18 + base*9 + dy*3 + 1];
            float c02 = sw[0*18 + base*9 + dy*3 + 2];
            float c10 = sw[1*18 + base*9 + dy*3 + 0];
            float c11 = sw[1*18 + base*9 + dy*3 + 1];
            float c12 = sw[1*18 + base*9 + dy*3 + 2];
            o0a += c00*w0 + c01*w1 + c02*w2;
            o0b += c00*w1 + c01*w2 + c02*w3;
            o1a += c10*w0 + c11*w1 + c12*w2;
            o1b += c10*w1 + c11*w2 + c12*w3;
        }
    }
    int p  = (ty0+py)*Ww + tx0 + px2;   // even
    int h4 = p >> 1;
    const float4* sp = reinterpret_cast<const float4*>(sens) + (size_t)b*COILS*(HW/2) + h4;
    float4*       op = reinterpret_cast<float4*>(out)        + (size_t)b*COILS*(HW/2) + h4;
    #pragma unroll
    for (int c = 0; c < COILS; c++){
        float4 s = __ldg(sp + (size_t)c*(HW/2));
        float4 r;
        r.x = o0a*s.x - o1a*s.y;
        r.y = o0a*s.y + o1a*s.x;
        r.z = o0b*s.z - o1b*s.w;
        r.w = o0b*s.w + o1b*s.z;
        op[(size_t)c*(HW/2)] = r;
    }
}

extern "C" void kernel_launch(void* const* d_in, const int* in_sizes, int n_in,
                              void* d_out, int out_size){
    const float* x      = (const float*)d_in[0];
    const float* e      = (const float*)d_in[1];
    const float* sens   = (const float*)d_in[2];
    const float* w_im1  = (const float*)d_in[3];
    const float* w_im2  = (const float*)d_in[4];
    const float* w_e    = (const float*)d_in[5];
    const float* w_proj = (const float*)d_in[6];
    const float* a1     = (const float*)d_in[7];
    float* out = (float*)d_out;

    void* gaddr = nullptr;
    cudaGetSymbolAddress(&gaddr, g_gram);
    cudaMemsetAsync(gaddr, 0, (size_t)Bz*729*sizeof(float), 0);

    k_cgram<<<dim3(Ww/32, Hh/32, Bz), 256>>>(x, sens, e);
    k_attn<<<Bz, 256>>>(w_im1, w_im2, w_e, w_proj, a1);
    k_output<<<dim3(Ww/64, Hh/8, Bz), 256>>>(sens, out);
}